// round 1
// baseline (speedup 1.0000x reference)
#include <cuda_runtime.h>
#include <cstdint>

// Problem constants (fixed by reference setup_inputs)
#define B_  8
#define C_  64
#define T_  12
#define N_  512
#define G_  (B_ * T_)      // 96
#define H_  4
#define CO_ 64
#define HC_ (H_ * CO_)     // 256
#define NEG_SLOPE 0.2f
#define EMAX 16384

// -------- device scratch (static __device__ arrays: allowed) --------
__device__ float g_h[(size_t)G_ * N_ * HC_];     // [G,N,256]  ~50 MB
__device__ float g_asrc[(size_t)G_ * N_ * H_];   // [G,N,H]
__device__ float g_adst[(size_t)G_ * N_ * H_];
__device__ int   g_rowptr[N_ + 1];
__device__ int   g_col[EMAX];

__device__ __forceinline__ float lrelu(float x) {
    return x > 0.0f ? x : NEG_SLOPE * x;
}

// ============================================================
// Kernel 1: CSR build from edge_index (dst-sorted), 1 block / 512 threads
// ============================================================
__global__ void csr_build_kernel(const int* __restrict__ ei, int E) {
    __shared__ int cnt[N_];
    __shared__ int cur[N_];
    __shared__ int wsum[16];
    int tid = threadIdx.x;
    cnt[tid] = 0;
    __syncthreads();
    const int* src = ei;
    const int* dst = ei + E;
    for (int e = tid; e < E; e += N_) atomicAdd(&cnt[dst[e]], 1);
    __syncthreads();

    // block exclusive scan of cnt[512]
    int v = cnt[tid];
    int lane = tid & 31, wid = tid >> 5;
    int inc = v;
    #pragma unroll
    for (int o = 1; o < 32; o <<= 1) {
        int u = __shfl_up_sync(0xffffffffu, inc, o);
        if (lane >= o) inc += u;
    }
    if (lane == 31) wsum[wid] = inc;
    __syncthreads();
    if (wid == 0 && lane < 16) {
        int ws = wsum[lane];
        int wi = ws;
        #pragma unroll
        for (int o = 1; o < 16; o <<= 1) {
            int u = __shfl_up_sync(0x0000ffffu, wi, o);
            if (lane >= o) wi += u;
        }
        wsum[lane] = wi - ws;   // exclusive warp offsets
    }
    __syncthreads();
    int excl = inc - v + wsum[wid];
    g_rowptr[tid] = excl;
    cur[tid] = excl;
    if (tid == N_ - 1) g_rowptr[N_] = excl + v;
    __syncthreads();

    for (int e = tid; e < E; e += N_) {
        int d = dst[e];
        int p = atomicAdd(&cur[d], 1);
        g_col[p] = src[e];
    }
}

// ============================================================
// Kernel 2: h = xg @ W   (per g: [512,64] @ [64,256])
// grid (16, 96), block 256. Each block: 32 nodes x 256 cols.
// ============================================================
__global__ void gemm_kernel(const float* __restrict__ x, const float* __restrict__ W) {
    __shared__ float xs[32][65];   // [n_local][c], padded
    int g  = blockIdx.y;
    int n0 = blockIdx.x * 32;
    int b  = g / T_;
    int t  = g - b * T_;
    int tid = threadIdx.x;

    // load x tile: xs[nl][c] = x[b, c, t, n0+nl]
    #pragma unroll
    for (int e = tid; e < 64 * 32; e += 256) {
        int c  = e >> 5;
        int nl = e & 31;
        xs[nl][c] = x[(((size_t)b * C_ + c) * T_ + t) * N_ + n0 + nl];
    }
    __syncthreads();

    int w    = tid >> 5;
    int lane = tid & 31;
    int col  = w * 32 + lane;

    float acc[32];
    #pragma unroll
    for (int n = 0; n < 32; n++) acc[n] = 0.0f;

    #pragma unroll 8
    for (int c = 0; c < 64; c++) {
        float wv = __ldg(&W[c * HC_ + col]);
        #pragma unroll
        for (int n = 0; n < 32; n++) acc[n] = fmaf(xs[n][c], wv, acc[n]);
    }

    float* hp = g_h + ((size_t)g * N_ + n0) * HC_ + col;
    #pragma unroll
    for (int n = 0; n < 32; n++) hp[(size_t)n * HC_] = acc[n];
}

// ============================================================
// Kernel 3: a_src/a_dst dot products. One warp per (g,n,h).
// ============================================================
__global__ void acompute_kernel(const float* __restrict__ att_src,
                                const float* __restrict__ att_dst) {
    int wgl  = (blockIdx.x * blockDim.x + threadIdx.x) >> 5;
    int lane = threadIdx.x & 31;
    if (wgl >= G_ * N_ * H_) return;
    int hh = wgl & (H_ - 1);
    int gn = wgl >> 2;                  // g*N + n

    float2 as = *(const float2*)(att_src + hh * CO_ + 2 * lane);
    float2 ad = *(const float2*)(att_dst + hh * CO_ + 2 * lane);
    float2 hv = *(const float2*)(g_h + (size_t)gn * HC_ + hh * CO_ + 2 * lane);
    float ps = hv.x * as.x + hv.y * as.y;
    float pd = hv.x * ad.x + hv.y * ad.y;
    #pragma unroll
    for (int o = 16; o > 0; o >>= 1) {
        ps += __shfl_xor_sync(0xffffffffu, ps, o);
        pd += __shfl_xor_sync(0xffffffffu, pd, o);
    }
    if (lane == 0) {
        g_asrc[(size_t)gn * H_ + hh] = ps;
        g_adst[(size_t)gn * H_ + hh] = pd;
    }
}

// ============================================================
// Kernel 4: per-(g,dst) softmax + weighted gather + head mean.
// grid (512, 96), block 128 (4 warps = 4 heads).
// ============================================================
__global__ void aggregate_kernel(const float* __restrict__ bias,
                                 float* __restrict__ out) {
    __shared__ float so[H_][CO_];
    int dst  = blockIdx.x;
    int g    = blockIdx.y;
    int hh   = threadIdx.x >> 5;
    int lane = threadIdx.x & 31;

    int start = g_rowptr[dst];
    int end   = g_rowptr[dst + 1];

    size_t gnd = (size_t)g * N_ + dst;
    float adst_v = g_adst[gnd * H_ + hh];
    float logit_self = lrelu(g_asrc[gnd * H_ + hh] + adst_v);

    // online softmax (max + sum), self-loop counted by lane 0
    float m_l = (lane == 0) ? logit_self : -1e30f;
    float s_l = (lane == 0) ? 1.0f : 0.0f;
    for (int e = start + lane; e < end; e += 32) {
        int src = g_col[e];
        float lg = lrelu(g_asrc[((size_t)g * N_ + src) * H_ + hh] + adst_v);
        if (lg > m_l) { s_l = s_l * __expf(m_l - lg) + 1.0f; m_l = lg; }
        else          { s_l += __expf(lg - m_l); }
    }
    #pragma unroll
    for (int o = 16; o > 0; o >>= 1) {
        float mo = __shfl_xor_sync(0xffffffffu, m_l, o);
        float so_ = __shfl_xor_sync(0xffffffffu, s_l, o);
        float mn = fmaxf(m_l, mo);
        s_l = s_l * __expf(m_l - mn) + so_ * __expf(mo - mn);
        m_l = mn;
    }

    // weighted gather: acc = sum_e w_e * h[src_e, hh, :]  (unnormalized)
    const float* hbase = g_h + (size_t)g * N_ * HC_ + hh * CO_ + 2 * lane;
    float w_self = __expf(logit_self - m_l);
    float2 hv = *(const float2*)(hbase + (size_t)dst * HC_);
    float accx = w_self * hv.x;
    float accy = w_self * hv.y;

    for (int base = start; base < end; base += 32) {
        int e   = base + lane;
        int src = 0;
        float w = 0.0f;
        if (e < end) {
            src = g_col[e];
            w = __expf(lrelu(g_asrc[((size_t)g * N_ + src) * H_ + hh] + adst_v) - m_l);
        }
        int cnt = min(32, end - base);
        for (int j = 0; j < cnt; j++) {
            float wj = __shfl_sync(0xffffffffu, w, j);
            int   sj = __shfl_sync(0xffffffffu, src, j);
            float2 hv2 = *(const float2*)(hbase + (size_t)sj * HC_);
            accx = fmaf(wj, hv2.x, accx);
            accy = fmaf(wj, hv2.y, accy);
        }
    }

    float inv = 1.0f / s_l;
    so[hh][2 * lane]     = accx * inv;
    so[hh][2 * lane + 1] = accy * inv;
    __syncthreads();

    if (threadIdx.x < CO_) {
        int co = threadIdx.x;
        float v = 0.25f * (so[0][co] + so[1][co] + so[2][co] + so[3][co]) + bias[co];
        int b = g / T_;
        int t = g - b * T_;
        out[(((size_t)b * CO_ + co) * T_ + t) * N_ + dst] = v;
    }
}

// ============================================================
extern "C" void kernel_launch(void* const* d_in, const int* in_sizes, int n_in,
                              void* d_out, int out_size) {
    const float* x        = (const float*)d_in[0];
    const int*   ei       = (const int*)  d_in[1];
    const float* W        = (const float*)d_in[2];
    const float* att_src  = (const float*)d_in[3];
    const float* att_dst  = (const float*)d_in[4];
    const float* bias     = (const float*)d_in[5];
    float*       out      = (float*)d_out;
    int E = in_sizes[1] / 2;

    csr_build_kernel<<<1, N_>>>(ei, E);
    gemm_kernel<<<dim3(N_ / 32, G_), 256>>>(x, W);
    {
        int warps = G_ * N_ * H_;
        int blocks = (warps * 32 + 255) / 256;
        acompute_kernel<<<blocks, 256>>>(att_src, att_dst);
    }
    aggregate_kernel<<<dim3(N_, G_), 128>>>(bias, out);
}

// round 2
// speedup vs baseline: 1.2128x; 1.2128x over previous
#include <cuda_runtime.h>
#include <cstdint>

#define B_  8
#define C_  64
#define T_  12
#define N_  512
#define G_  (B_ * T_)      // 96
#define H_  4
#define CO_ 64
#define HC_ (H_ * CO_)     // 256
#define NEG_SLOPE 0.2f
#define EMAX 16384

__device__ float g_h[(size_t)G_ * N_ * HC_];      // [G,N,256]
__device__ float g_asrc[(size_t)G_ * N_ * H_];    // [G,N,4]
__device__ float g_adst[(size_t)G_ * N_ * H_];
__device__ float g_outs[(size_t)G_ * N_ * CO_];   // [G,N,64] scratch
__device__ int   g_rowptr[N_ + 1];
__device__ int   g_col[EMAX];

__device__ __forceinline__ float lrelu(float x) {
    return x > 0.0f ? x : NEG_SLOPE * x;
}

// ============================================================
// Kernel 1: CSR build (dst-sorted), 1 block / 512 threads
// ============================================================
__global__ void csr_build_kernel(const int* __restrict__ ei, int E) {
    __shared__ int cnt[N_];
    __shared__ int cur[N_];
    __shared__ int wsum[16];
    int tid = threadIdx.x;
    cnt[tid] = 0;
    __syncthreads();
    const int* src = ei;
    const int* dst = ei + E;
    for (int e = tid; e < E; e += N_) atomicAdd(&cnt[dst[e]], 1);
    __syncthreads();

    int v = cnt[tid];
    int lane = tid & 31, wid = tid >> 5;
    int inc = v;
    #pragma unroll
    for (int o = 1; o < 32; o <<= 1) {
        int u = __shfl_up_sync(0xffffffffu, inc, o);
        if (lane >= o) inc += u;
    }
    if (lane == 31) wsum[wid] = inc;
    __syncthreads();
    if (wid == 0 && lane < 16) {
        int ws = wsum[lane];
        int wi = ws;
        #pragma unroll
        for (int o = 1; o < 16; o <<= 1) {
            int u = __shfl_up_sync(0x0000ffffu, wi, o);
            if (lane >= o) wi += u;
        }
        wsum[lane] = wi - ws;
    }
    __syncthreads();
    int excl = inc - v + wsum[wid];
    g_rowptr[tid] = excl;
    cur[tid] = excl;
    if (tid == N_ - 1) g_rowptr[N_] = excl + v;
    __syncthreads();

    for (int e = tid; e < E; e += N_) {
        int d = dst[e];
        int p = atomicAdd(&cur[d], 1);
        g_col[p] = src[e];
    }
}

// ============================================================
// Kernel 2: h = xg @ W.  Tile 64 nodes x 64 cols, 4x4 microtile.
// grid (8 nodeblk, 4 colblk, 96), block 256.
// ============================================================
__global__ void gemm_kernel(const float* __restrict__ x, const float* __restrict__ W) {
    __shared__ float xs[64][64];   // [c][n]
    __shared__ float ws[64][64];   // [c][col]
    int n0   = blockIdx.x * 64;
    int col0 = blockIdx.y * 64;
    int g    = blockIdx.z;
    int b    = g / T_;
    int t    = g - b * T_;
    int tid  = threadIdx.x;

    #pragma unroll
    for (int i = tid; i < 64 * 16; i += 256) {
        int c = i >> 4, q = i & 15;
        float4 vx = *(const float4*)(x + (((size_t)b * C_ + c) * T_ + t) * N_ + n0 + q * 4);
        *(float4*)&xs[c][q * 4] = vx;
        float4 vw = *(const float4*)(W + (size_t)c * HC_ + col0 + q * 4);
        *(float4*)&ws[c][q * 4] = vw;
    }
    __syncthreads();

    int ty = tid >> 4;   // node group 0..15
    int tx = tid & 15;   // col group 0..15

    float acc[4][4];
    #pragma unroll
    for (int i = 0; i < 4; i++)
        #pragma unroll
        for (int j = 0; j < 4; j++) acc[i][j] = 0.0f;

    #pragma unroll 16
    for (int c = 0; c < 64; c++) {
        float4 xv = *(const float4*)&xs[c][ty * 4];
        float4 wv = *(const float4*)&ws[c][tx * 4];
        float xa[4] = {xv.x, xv.y, xv.z, xv.w};
        float wa[4] = {wv.x, wv.y, wv.z, wv.w};
        #pragma unroll
        for (int i = 0; i < 4; i++)
            #pragma unroll
            for (int j = 0; j < 4; j++)
                acc[i][j] = fmaf(xa[i], wa[j], acc[i][j]);
    }

    #pragma unroll
    for (int i = 0; i < 4; i++) {
        float* hp = g_h + ((size_t)g * N_ + n0 + ty * 4 + i) * HC_ + col0 + tx * 4;
        float4 v = {acc[i][0], acc[i][1], acc[i][2], acc[i][3]};
        *(float4*)hp = v;
    }
}

// ============================================================
// Kernel 3: a_src/a_dst. One warp per (g,n), all 4 heads.
// ============================================================
__global__ void acompute_kernel(const float* __restrict__ att_src,
                                const float* __restrict__ att_dst) {
    int gn   = blockIdx.x * 8 + (threadIdx.x >> 5);   // g*N + n
    int lane = threadIdx.x & 31;
    int myh  = lane >> 3;
    int cob  = (lane & 7) * 8;

    const float4* hp = (const float4*)(g_h + (size_t)gn * HC_) + (lane << 1);
    float4 h0 = hp[0], h1 = hp[1];
    const float4* ap = (const float4*)(att_src + myh * CO_ + cob);
    const float4* dp = (const float4*)(att_dst + myh * CO_ + cob);
    float4 a0 = ap[0], a1 = ap[1];
    float4 d0 = dp[0], d1 = dp[1];

    float ps = h0.x * a0.x + h0.y * a0.y + h0.z * a0.z + h0.w * a0.w
             + h1.x * a1.x + h1.y * a1.y + h1.z * a1.z + h1.w * a1.w;
    float pd = h0.x * d0.x + h0.y * d0.y + h0.z * d0.z + h0.w * d0.w
             + h1.x * d1.x + h1.y * d1.y + h1.z * d1.z + h1.w * d1.w;
    #pragma unroll
    for (int o = 4; o > 0; o >>= 1) {
        ps += __shfl_xor_sync(0xffffffffu, ps, o);
        pd += __shfl_xor_sync(0xffffffffu, pd, o);
    }
    if ((lane & 7) == 0) {
        g_asrc[(size_t)gn * H_ + myh] = ps;
        g_adst[(size_t)gn * H_ + myh] = pd;
    }
}

// ============================================================
// Kernel 4: warp per (g,dst), all 4 heads; a_src table in smem.
// grid (64, 96), block 256 (8 warps = 8 dst).
// ============================================================
__global__ void aggregate_kernel(const float* __restrict__ bias) {
    __shared__ float4 s_as[N_];
    int g    = blockIdx.y;
    int tid  = threadIdx.x;
    int warp = tid >> 5, lane = tid & 31;

    const float4* asrc_g = (const float4*)(g_asrc + (size_t)g * N_ * H_);
    for (int i = tid; i < N_; i += 256) s_as[i] = asrc_g[i];
    __syncthreads();

    int dst = (blockIdx.x << 3) + warp;
    int start = g_rowptr[dst];
    int end   = g_rowptr[dst + 1];

    float4 ad = *(const float4*)(g_adst + ((size_t)g * N_ + dst) * H_);
    float4 sa = s_as[dst];
    float ls0 = lrelu(sa.x + ad.x), ls1 = lrelu(sa.y + ad.y);
    float ls2 = lrelu(sa.z + ad.z), ls3 = lrelu(sa.w + ad.w);

    // ---- max pass ----
    float m0 = ls0, m1 = ls1, m2 = ls2, m3 = ls3;
    for (int e = start + lane; e < end; e += 32) {
        float4 a = s_as[g_col[e]];
        m0 = fmaxf(m0, lrelu(a.x + ad.x));
        m1 = fmaxf(m1, lrelu(a.y + ad.y));
        m2 = fmaxf(m2, lrelu(a.z + ad.z));
        m3 = fmaxf(m3, lrelu(a.w + ad.w));
    }
    #pragma unroll
    for (int o = 16; o > 0; o >>= 1) {
        m0 = fmaxf(m0, __shfl_xor_sync(0xffffffffu, m0, o));
        m1 = fmaxf(m1, __shfl_xor_sync(0xffffffffu, m1, o));
        m2 = fmaxf(m2, __shfl_xor_sync(0xffffffffu, m2, o));
        m3 = fmaxf(m3, __shfl_xor_sync(0xffffffffu, m3, o));
    }

    // ---- sum pass ----
    float s0 = (lane == 0) ? __expf(ls0 - m0) : 0.0f;
    float s1 = (lane == 0) ? __expf(ls1 - m1) : 0.0f;
    float s2 = (lane == 0) ? __expf(ls2 - m2) : 0.0f;
    float s3 = (lane == 0) ? __expf(ls3 - m3) : 0.0f;
    for (int e = start + lane; e < end; e += 32) {
        float4 a = s_as[g_col[e]];
        s0 += __expf(lrelu(a.x + ad.x) - m0);
        s1 += __expf(lrelu(a.y + ad.y) - m1);
        s2 += __expf(lrelu(a.z + ad.z) - m2);
        s3 += __expf(lrelu(a.w + ad.w) - m3);
    }
    #pragma unroll
    for (int o = 16; o > 0; o >>= 1) {
        s0 += __shfl_xor_sync(0xffffffffu, s0, o);
        s1 += __shfl_xor_sync(0xffffffffu, s1, o);
        s2 += __shfl_xor_sync(0xffffffffu, s2, o);
        s3 += __shfl_xor_sync(0xffffffffu, s3, o);
    }

    int myh  = lane >> 3;
    float mh  = myh == 0 ? m0 : myh == 1 ? m1 : myh == 2 ? m2 : m3;
    float lsh = myh == 0 ? ls0 : myh == 1 ? ls1 : myh == 2 ? ls2 : ls3;
    float sh  = myh == 0 ? s0 : myh == 1 ? s1 : myh == 2 ? s2 : s3;
    float inv = 1.0f / sh;

    const float* hbase = g_h + (size_t)g * N_ * HC_;

    // self-loop contribution
    float wself = __expf(lsh - mh);
    const float4* sp = (const float4*)(hbase + (size_t)dst * HC_) + (lane << 1);
    float4 h0 = sp[0], h1 = sp[1];
    float4 c0, c1;
    c0.x = wself * h0.x; c0.y = wself * h0.y; c0.z = wself * h0.z; c0.w = wself * h0.w;
    c1.x = wself * h1.x; c1.y = wself * h1.y; c1.z = wself * h1.z; c1.w = wself * h1.w;

    for (int base = start; base < end; base += 32) {
        int e = base + lane;
        int src = 0;
        float w0 = 0.f, w1 = 0.f, w2 = 0.f, w3 = 0.f;
        if (e < end) {
            src = g_col[e];
            float4 a = s_as[src];
            w0 = __expf(lrelu(a.x + ad.x) - m0);
            w1 = __expf(lrelu(a.y + ad.y) - m1);
            w2 = __expf(lrelu(a.z + ad.z) - m2);
            w3 = __expf(lrelu(a.w + ad.w) - m3);
        }
        int cnt = min(32, end - base);
        for (int j = 0; j < cnt; j++) {
            int   sj = __shfl_sync(0xffffffffu, src, j);
            float b0 = __shfl_sync(0xffffffffu, w0, j);
            float b1 = __shfl_sync(0xffffffffu, w1, j);
            float b2 = __shfl_sync(0xffffffffu, w2, j);
            float b3 = __shfl_sync(0xffffffffu, w3, j);
            float w = myh == 0 ? b0 : myh == 1 ? b1 : myh == 2 ? b2 : b3;
            const float4* hp = (const float4*)(hbase + (size_t)sj * HC_) + (lane << 1);
            float4 v0 = hp[0], v1 = hp[1];
            c0.x = fmaf(w, v0.x, c0.x); c0.y = fmaf(w, v0.y, c0.y);
            c0.z = fmaf(w, v0.z, c0.z); c0.w = fmaf(w, v0.w, c0.w);
            c1.x = fmaf(w, v1.x, c1.x); c1.y = fmaf(w, v1.y, c1.y);
            c1.z = fmaf(w, v1.z, c1.z); c1.w = fmaf(w, v1.w, c1.w);
        }
    }

    // normalize by softmax sum
    c0.x *= inv; c0.y *= inv; c0.z *= inv; c0.w *= inv;
    c1.x *= inv; c1.y *= inv; c1.z *= inv; c1.w *= inv;

    // head mean: reduce across lanes differing in bits 3,4 (same co, different head)
    c0.x += __shfl_xor_sync(0xffffffffu, c0.x, 8);  c0.x += __shfl_xor_sync(0xffffffffu, c0.x, 16);
    c0.y += __shfl_xor_sync(0xffffffffu, c0.y, 8);  c0.y += __shfl_xor_sync(0xffffffffu, c0.y, 16);
    c0.z += __shfl_xor_sync(0xffffffffu, c0.z, 8);  c0.z += __shfl_xor_sync(0xffffffffu, c0.z, 16);
    c0.w += __shfl_xor_sync(0xffffffffu, c0.w, 8);  c0.w += __shfl_xor_sync(0xffffffffu, c0.w, 16);
    c1.x += __shfl_xor_sync(0xffffffffu, c1.x, 8);  c1.x += __shfl_xor_sync(0xffffffffu, c1.x, 16);
    c1.y += __shfl_xor_sync(0xffffffffu, c1.y, 8);  c1.y += __shfl_xor_sync(0xffffffffu, c1.y, 16);
    c1.z += __shfl_xor_sync(0xffffffffu, c1.z, 8);  c1.z += __shfl_xor_sync(0xffffffffu, c1.z, 16);
    c1.w += __shfl_xor_sync(0xffffffffu, c1.w, 8);  c1.w += __shfl_xor_sync(0xffffffffu, c1.w, 16);

    if (lane < 8) {
        const float4* bp = (const float4*)bias + (lane << 1);
        float4 b0 = bp[0], b1 = bp[1];
        float4 r0, r1;
        r0.x = 0.25f * c0.x + b0.x; r0.y = 0.25f * c0.y + b0.y;
        r0.z = 0.25f * c0.z + b0.z; r0.w = 0.25f * c0.w + b0.w;
        r1.x = 0.25f * c1.x + b1.x; r1.y = 0.25f * c1.y + b1.y;
        r1.z = 0.25f * c1.z + b1.z; r1.w = 0.25f * c1.w + b1.w;
        float4* op = (float4*)(g_outs + ((size_t)g * N_ + dst) * CO_) + (lane << 1);
        op[0] = r0; op[1] = r1;
    }
}

// ============================================================
// Kernel 5: transpose [G,N,Co] -> [B,Co,T,N]. grid (8, 96), block 256.
// ============================================================
__global__ void transpose_kernel(float* __restrict__ out) {
    __shared__ float s[64][65];
    int g  = blockIdx.y;
    int n0 = blockIdx.x * 64;
    int b  = g / T_;
    int t  = g - b * T_;
    int tid = threadIdx.x;

    const float* src = g_outs + ((size_t)g * N_ + n0) * CO_;
    #pragma unroll
    for (int i = tid; i < 64 * 16; i += 256) {
        int n = i >> 4, q = i & 15;
        float4 v = *(const float4*)(src + (size_t)n * CO_ + q * 4);
        s[n][q * 4 + 0] = v.x; s[n][q * 4 + 1] = v.y;
        s[n][q * 4 + 2] = v.z; s[n][q * 4 + 3] = v.w;
    }
    __syncthreads();

    int co = tid >> 2, q = tid & 3;
    float* ob = out + (((size_t)b * CO_ + co) * T_ + t) * N_ + n0;
    #pragma unroll
    for (int r = 0; r < 4; r++) {
        int nb = q * 16 + r * 4;
        float4 v = {s[nb][co], s[nb + 1][co], s[nb + 2][co], s[nb + 3][co]};
        *(float4*)(ob + nb) = v;
    }
}

// ============================================================
extern "C" void kernel_launch(void* const* d_in, const int* in_sizes, int n_in,
                              void* d_out, int out_size) {
    const float* x        = (const float*)d_in[0];
    const int*   ei       = (const int*)  d_in[1];
    const float* W        = (const float*)d_in[2];
    const float* att_src  = (const float*)d_in[3];
    const float* att_dst  = (const float*)d_in[4];
    const float* bias     = (const float*)d_in[5];
    float*       out      = (float*)d_out;
    int E = in_sizes[1] / 2;

    csr_build_kernel<<<1, N_>>>(ei, E);
    gemm_kernel<<<dim3(8, 4, G_), 256>>>(x, W);
    acompute_kernel<<<G_ * N_ / 8, 256>>>(att_src, att_dst);
    aggregate_kernel<<<dim3(N_ / 8, G_), 256>>>(bias);
    transpose_kernel<<<dim3(N_ / 64, G_), 256>>>(out);
}

// round 3
// speedup vs baseline: 1.4655x; 1.2084x over previous
#include <cuda_runtime.h>
#include <cstdint>

#define B_  8
#define C_  64
#define T_  12
#define N_  512
#define G_  (B_ * T_)      // 96
#define H_  4
#define CO_ 64
#define HC_ (H_ * CO_)     // 256
#define NEG_SLOPE 0.2f
#define EMAX 16384

typedef unsigned long long ull;

// ---------------- device scratch ----------------
__device__ float g_xt[(size_t)G_ * N_ * C_];     // [G,N,64]  x transposed
__device__ float g_z [(size_t)G_ * N_ * HC_];    // [G,N,256] aggregated per head
__device__ float g_asrc[(size_t)G_ * N_ * H_];   // [G,N,4]
__device__ float g_adst[(size_t)G_ * N_ * H_];
__device__ float g_u[2 * H_ * C_];               // [src/dst][h][c]
__device__ float g_Wt[HC_ * CO_];                // Wt[h*64+c][co] = 0.25*W[c][h*64+co]
__device__ int   g_rowptr[N_ + 1];
__device__ int   g_col[EMAX];

__device__ __forceinline__ float lrelu(float x) {
    return x > 0.0f ? x : NEG_SLOPE * x;
}

__device__ __forceinline__ ull pack2(float lo, float hi) {
    ull d;
    asm("mov.b64 %0, {%1, %2};" : "=l"(d) : "r"(__float_as_uint(lo)), "r"(__float_as_uint(hi)));
    return d;
}
__device__ __forceinline__ void unpack2(ull v, float& lo, float& hi) {
    unsigned a, b;
    asm("mov.b64 {%0, %1}, %2;" : "=r"(a), "=r"(b) : "l"(v));
    lo = __uint_as_float(a); hi = __uint_as_float(b);
}
__device__ __forceinline__ ull fma2(ull a, ull b, ull c) {
    ull d;
    asm("fma.rn.f32x2 %0, %1, %2, %3;" : "=l"(d) : "l"(a), "l"(b), "l"(c));
    return d;
}

// ============================================================
// K0: CSR build (dst-sorted), 1 block / 512 threads
// ============================================================
__global__ void csr_build_kernel(const int* __restrict__ ei, int E) {
    __shared__ int cnt[N_];
    __shared__ int cur[N_];
    __shared__ int wsum[16];
    int tid = threadIdx.x;
    cnt[tid] = 0;
    __syncthreads();
    const int* src = ei;
    const int* dst = ei + E;
    for (int e = tid; e < E; e += N_) atomicAdd(&cnt[dst[e]], 1);
    __syncthreads();

    int v = cnt[tid];
    int lane = tid & 31, wid = tid >> 5;
    int inc = v;
    #pragma unroll
    for (int o = 1; o < 32; o <<= 1) {
        int u = __shfl_up_sync(0xffffffffu, inc, o);
        if (lane >= o) inc += u;
    }
    if (lane == 31) wsum[wid] = inc;
    __syncthreads();
    if (wid == 0 && lane < 16) {
        int ws = wsum[lane];
        int wi = ws;
        #pragma unroll
        for (int o = 1; o < 16; o <<= 1) {
            int u = __shfl_up_sync(0x0000ffffu, wi, o);
            if (lane >= o) wi += u;
        }
        wsum[lane] = wi - ws;
    }
    __syncthreads();
    int excl = inc - v + wsum[wid];
    g_rowptr[tid] = excl;
    cur[tid] = excl;
    if (tid == N_ - 1) g_rowptr[N_] = excl + v;
    __syncthreads();

    for (int e = tid; e < E; e += N_) {
        int d = dst[e];
        int p = atomicAdd(&cur[d], 1);
        g_col[p] = src[e];
    }
}

// ============================================================
// K1: prep  u[p][h][c] = sum_co W[c][h*64+co]*att_{p}[h][co]
//          Wt[h*64+c][co] = 0.25*W[c][h*64+co]
// 1 block, 256 threads.
// ============================================================
__global__ void prep_kernel(const float* __restrict__ W,
                            const float* __restrict__ att_src,
                            const float* __restrict__ att_dst) {
    __shared__ float satt[2][H_ * CO_];
    int tid = threadIdx.x;
    satt[0][tid] = att_src[tid];
    satt[1][tid] = att_dst[tid];
    __syncthreads();

    for (int k = tid; k < 2 * H_ * C_; k += 256) {
        int p = k >> 8;
        int h = (k >> 6) & 3;
        int c = k & 63;
        const float* wrow = W + (size_t)c * HC_ + h * CO_;
        float s = 0.0f;
        #pragma unroll 16
        for (int co = 0; co < CO_; co++) s += wrow[co] * satt[p][h * CO_ + co];
        g_u[k] = s;
    }
    for (int idx = tid; idx < HC_ * CO_; idx += 256) {
        int kk = idx >> 6;   // h*64+c
        int co = idx & 63;
        int h = kk >> 6, c = kk & 63;
        g_Wt[idx] = 0.25f * W[(size_t)c * HC_ + h * CO_ + co];
    }
}

// ============================================================
// K2: per g: transpose x -> xt[g][n][c], and asrc/adst = xt . u
// grid (4, 96), block 256.
// ============================================================
__global__ void xt_asrc_kernel(const float* __restrict__ x) {
    __shared__ float xs[64][129];
    __shared__ float su[8][64];
    int g  = blockIdx.y;
    int n0 = blockIdx.x * 128;
    int b  = g / T_;
    int t  = g - b * T_;
    int tid = threadIdx.x;

    for (int i = tid; i < 512; i += 256) su[i >> 6][i & 63] = g_u[i];
    #pragma unroll
    for (int i = tid; i < 64 * 32; i += 256) {
        int c = i >> 5, q = i & 31;
        float4 v = *(const float4*)(x + (((size_t)b * C_ + c) * T_ + t) * N_ + n0 + q * 4);
        xs[c][q * 4 + 0] = v.x; xs[c][q * 4 + 1] = v.y;
        xs[c][q * 4 + 2] = v.z; xs[c][q * 4 + 3] = v.w;
    }
    __syncthreads();

    // asrc/adst: thread -> (n, p)
    {
        int n = tid & 127;
        int p = tid >> 7;
        float a0 = 0.f, a1 = 0.f, a2 = 0.f, a3 = 0.f;
        #pragma unroll 16
        for (int c = 0; c < 64; c++) {
            float xv = xs[c][n];
            a0 = fmaf(xv, su[p * 4 + 0][c], a0);
            a1 = fmaf(xv, su[p * 4 + 1][c], a1);
            a2 = fmaf(xv, su[p * 4 + 2][c], a2);
            a3 = fmaf(xv, su[p * 4 + 3][c], a3);
        }
        float* dstp = (p == 0 ? g_asrc : g_adst) + ((size_t)g * N_ + n0 + n) * H_;
        dstp[0] = a0; dstp[1] = a1; dstp[2] = a2; dstp[3] = a3;
    }

    // xt write: [G,N,64]
    #pragma unroll
    for (int i = tid; i < 128 * 16; i += 256) {
        int n = i >> 4, q = i & 15;
        float4 v = {xs[q * 4 + 0][n], xs[q * 4 + 1][n], xs[q * 4 + 2][n], xs[q * 4 + 3][n]};
        *(float4*)(g_xt + ((size_t)g * N_ + n0 + n) * C_ + q * 4) = v;
    }
}

// ============================================================
// K3: aggregate in x-space. warp per (g,dst), single pass softmax
// (no max subtraction: logits bounded, exp safe in fp32).
// z[g,dst,h*64+c] = (1/s_h) * sum_{src in N(dst)+self} w_h(src) x[src,c]
// grid (64, 96), block 256 (8 warps).
// ============================================================
__global__ void aggregate_kernel() {
    __shared__ float4 s_as[N_];
    int g    = blockIdx.y;
    int tid  = threadIdx.x;
    int warp = tid >> 5, lane = tid & 31;

    const float4* asrc_g = (const float4*)(g_asrc + (size_t)g * N_ * H_);
    for (int i = tid; i < N_; i += 256) s_as[i] = asrc_g[i];
    __syncthreads();

    int dst   = (blockIdx.x << 3) + warp;
    int start = g_rowptr[dst];
    int end   = g_rowptr[dst + 1];

    float4 ad = *(const float4*)(g_adst + ((size_t)g * N_ + dst) * H_);
    float4 sa = s_as[dst];
    float ws0 = __expf(lrelu(sa.x + ad.x));
    float ws1 = __expf(lrelu(sa.y + ad.y));
    float ws2 = __expf(lrelu(sa.z + ad.z));
    float ws3 = __expf(lrelu(sa.w + ad.w));

    const float* xg = g_xt + (size_t)g * N_ * C_;
    float2 xd = *((const float2*)(xg + (size_t)dst * C_) + lane);
    float2 a0 = {ws0 * xd.x, ws0 * xd.y};
    float2 a1 = {ws1 * xd.x, ws1 * xd.y};
    float2 a2 = {ws2 * xd.x, ws2 * xd.y};
    float2 a3 = {ws3 * xd.x, ws3 * xd.y};

    float p0 = 0.f, p1 = 0.f, p2 = 0.f, p3 = 0.f;   // per-lane partial sums

    for (int base = start; base < end; base += 32) {
        int e = base + lane;
        int src = 0;
        float w0 = 0.f, w1 = 0.f, w2 = 0.f, w3 = 0.f;
        if (e < end) {
            src = g_col[e];
            float4 a = s_as[src];
            w0 = __expf(lrelu(a.x + ad.x));
            w1 = __expf(lrelu(a.y + ad.y));
            w2 = __expf(lrelu(a.z + ad.z));
            w3 = __expf(lrelu(a.w + ad.w));
        }
        p0 += w0; p1 += w1; p2 += w2; p3 += w3;
        int cnt = min(32, end - base);
        for (int j = 0; j < cnt; j++) {
            int   sj = __shfl_sync(0xffffffffu, src, j);
            float b0 = __shfl_sync(0xffffffffu, w0, j);
            float b1 = __shfl_sync(0xffffffffu, w1, j);
            float b2 = __shfl_sync(0xffffffffu, w2, j);
            float b3 = __shfl_sync(0xffffffffu, w3, j);
            float2 xv = *((const float2*)(xg + (size_t)sj * C_) + lane);
            a0.x = fmaf(b0, xv.x, a0.x); a0.y = fmaf(b0, xv.y, a0.y);
            a1.x = fmaf(b1, xv.x, a1.x); a1.y = fmaf(b1, xv.y, a1.y);
            a2.x = fmaf(b2, xv.x, a2.x); a2.y = fmaf(b2, xv.y, a2.y);
            a3.x = fmaf(b3, xv.x, a3.x); a3.y = fmaf(b3, xv.y, a3.y);
        }
    }

    #pragma unroll
    for (int o = 16; o > 0; o >>= 1) {
        p0 += __shfl_xor_sync(0xffffffffu, p0, o);
        p1 += __shfl_xor_sync(0xffffffffu, p1, o);
        p2 += __shfl_xor_sync(0xffffffffu, p2, o);
        p3 += __shfl_xor_sync(0xffffffffu, p3, o);
    }
    float i0 = 1.0f / (p0 + ws0);
    float i1 = 1.0f / (p1 + ws1);
    float i2 = 1.0f / (p2 + ws2);
    float i3 = 1.0f / (p3 + ws3);

    float* zp = g_z + ((size_t)g * N_ + dst) * HC_ + 2 * lane;
    *(float2*)(zp +   0) = make_float2(a0.x * i0, a0.y * i0);
    *(float2*)(zp +  64) = make_float2(a1.x * i1, a1.y * i1);
    *(float2*)(zp + 128) = make_float2(a2.x * i2, a2.y * i2);
    *(float2*)(zp + 192) = make_float2(a3.x * i3, a3.y * i3);
}

// ============================================================
// K4: out = z @ Wt + bias, written directly as [B,Co,T,N].
// grid (8 nodeblk, 96), block 256. f32x2 packed FMA.
// ============================================================
__global__ void gemm2_kernel(const float* __restrict__ bias,
                             float* __restrict__ out) {
    __shared__ float zs[64][68];    // [n][k], padded for float4 align + banks
    __shared__ float ws[64][64];    // [k][co]
    __shared__ float os[64][68];    // [co][n]
    __shared__ float sbias[64];
    int g  = blockIdx.y;
    int n0 = blockIdx.x * 64;
    int b  = g / T_;
    int t  = g - b * T_;
    int tid = threadIdx.x;
    int ty = tid >> 4;   // n quad 0..15
    int tx = tid & 15;   // co quad 0..15

    if (tid < 64) sbias[tid] = bias[tid];

    ull acc2[4][2];
    #pragma unroll
    for (int i = 0; i < 4; i++) { acc2[i][0] = pack2(0.f, 0.f); acc2[i][1] = pack2(0.f, 0.f); }

    for (int kk = 0; kk < 4; kk++) {
        __syncthreads();
        #pragma unroll
        for (int i = tid; i < 64 * 16; i += 256) {
            int n = i >> 4, q = i & 15;
            float4 v = *(const float4*)(g_z + ((size_t)g * N_ + n0 + n) * HC_ + kk * 64 + q * 4);
            *(float4*)&zs[n][q * 4] = v;
            float4 w = *(const float4*)(g_Wt + (size_t)(kk * 64 + n) * CO_ + q * 4);
            *(float4*)&ws[n][q * 4] = w;
        }
        __syncthreads();

        #pragma unroll 8
        for (int c = 0; c < 64; c++) {
            float4 wv = *(const float4*)&ws[c][tx * 4];
            ull w01 = pack2(wv.x, wv.y);
            ull w23 = pack2(wv.z, wv.w);
            float z0 = zs[ty * 4 + 0][c];
            float z1 = zs[ty * 4 + 1][c];
            float z2 = zs[ty * 4 + 2][c];
            float z3 = zs[ty * 4 + 3][c];
            ull s0 = pack2(z0, z0), s1 = pack2(z1, z1);
            ull s2 = pack2(z2, z2), s3 = pack2(z3, z3);
            acc2[0][0] = fma2(s0, w01, acc2[0][0]); acc2[0][1] = fma2(s0, w23, acc2[0][1]);
            acc2[1][0] = fma2(s1, w01, acc2[1][0]); acc2[1][1] = fma2(s1, w23, acc2[1][1]);
            acc2[2][0] = fma2(s2, w01, acc2[2][0]); acc2[2][1] = fma2(s2, w23, acc2[2][1]);
            acc2[3][0] = fma2(s3, w01, acc2[3][0]); acc2[3][1] = fma2(s3, w23, acc2[3][1]);
        }
    }
    __syncthreads();

    // stage to os[co][n] with bias
    #pragma unroll
    for (int i = 0; i < 4; i++) {
        int n = ty * 4 + i;
        #pragma unroll
        for (int jp = 0; jp < 2; jp++) {
            float lo, hi;
            unpack2(acc2[i][jp], lo, hi);
            int co = tx * 4 + jp * 2;
            os[co][n]     = lo + sbias[co];
            os[co + 1][n] = hi + sbias[co + 1];
        }
    }
    __syncthreads();

    // coalesced write out[b, co, t, n0..]
    #pragma unroll
    for (int i = tid; i < 64 * 16; i += 256) {
        int co = i >> 4, q = i & 15;
        float4 v = *(const float4*)&os[co][q * 4];
        *(float4*)(out + (((size_t)b * CO_ + co) * T_ + t) * N_ + n0 + q * 4) = v;
    }
}

// ============================================================
extern "C" void kernel_launch(void* const* d_in, const int* in_sizes, int n_in,
                              void* d_out, int out_size) {
    const float* x        = (const float*)d_in[0];
    const int*   ei       = (const int*)  d_in[1];
    const float* W        = (const float*)d_in[2];
    const float* att_src  = (const float*)d_in[3];
    const float* att_dst  = (const float*)d_in[4];
    const float* bias     = (const float*)d_in[5];
    float*       out      = (float*)d_out;
    int E = in_sizes[1] / 2;

    csr_build_kernel<<<1, N_>>>(ei, E);
    prep_kernel<<<1, 256>>>(W, att_src, att_dst);
    xt_asrc_kernel<<<dim3(N_ / 128, G_), 256>>>(x);
    aggregate_kernel<<<dim3(N_ / 8, G_), 256>>>();
    gemm2_kernel<<<dim3(N_ / 64, G_), 256>>>(bias, out);
}